// round 9
// baseline (speedup 1.0000x reference)
#include <cuda_runtime.h>
#include <cuda_fp16.h>
#include <cstdint>

#define N_NODES  50000
#define N_EDGES  400000
#define N_GRAPHS 64

// ============================ device scratch ===============================
__device__ __half g_w1[256 * 512];         // [W1l|W1r]^T fp16  [256 n][512 k]
__device__ __half g_w2[64 * 128];          // [W2l|W2r]^T fp16  [64 n][128 k]
__device__ float g_y1[N_NODES * 256];
__device__ float g_agg1[N_NODES * 128];
__device__ float g_cnt[N_NODES];
__device__ float g_y2[N_NODES * 64];
__device__ float g_agg2[N_NODES * 32];
__device__ float g_gsum[N_GRAPHS * 32];
__device__ float g_gcnt[N_GRAPHS];

// ============================ zero accumulators ============================
__global__ void zero_kernel() {
    size_t i = (size_t)blockIdx.x * blockDim.x + threadIdx.x;
    size_t stride = (size_t)gridDim.x * blockDim.x;
    for (size_t k = i; k < (size_t)N_NODES * 128; k += stride) g_agg1[k] = 0.f;
    for (size_t k = i; k < (size_t)N_NODES * 32;  k += stride) g_agg2[k] = 0.f;
    for (size_t k = i; k < (size_t)N_NODES;       k += stride) g_cnt[k]  = 0.f;
    for (size_t k = i; k < (size_t)N_GRAPHS * 32; k += stride) g_gsum[k] = 0.f;
    for (size_t k = i; k < (size_t)N_GRAPHS;      k += stride) g_gcnt[k] = 0.f;
}

// ============================ helpers ======================================
__device__ __forceinline__ uint32_t su32(const void* p) {
    return (uint32_t)__cvta_generic_to_shared(p);
}
__device__ __forceinline__ uint32_t pack_h2(__half a, __half b) {
    __half2 t = __halves2half2(a, b);
    return *(uint32_t*)&t;
}
__device__ __forceinline__ uint2 cvt4h(float4 v) {
    return make_uint2(pack_h2(__float2half_rn(v.x), __float2half_rn(v.y)),
                      pack_h2(__float2half_rn(v.z), __float2half_rn(v.w)));
}
__device__ __forceinline__ void mma16816h(float* c, const uint32_t* a, const uint32_t* b) {
    asm volatile(
        "mma.sync.aligned.m16n8k16.row.col.f32.f16.f16.f32 "
        "{%0,%1,%2,%3}, {%4,%5,%6,%7}, {%8,%9}, {%0,%1,%2,%3};"
        : "+f"(c[0]), "+f"(c[1]), "+f"(c[2]), "+f"(c[3])
        : "r"(a[0]), "r"(a[1]), "r"(a[2]), "r"(a[3]), "r"(b[0]), "r"(b[1]));
}
__device__ __forceinline__ void ldsm4(uint32_t* r, uint32_t addr) {
    asm volatile("ldmatrix.sync.aligned.m8n8.x4.shared.b16 {%0,%1,%2,%3}, [%4];"
                 : "=r"(r[0]), "=r"(r[1]), "=r"(r[2]), "=r"(r[3]) : "r"(addr));
}

// ==================== weight conversions (fp16) =============================
__global__ void convert_w(const float* __restrict__ Wl, const float* __restrict__ Wr) {
    int idx = blockIdx.x * blockDim.x + threadIdx.x;
    if (idx >= 256 * 512) return;
    int n = idx >> 9, k = idx & 511;
    float v = (n < 128) ? Wl[k * 128 + n] : Wr[k * 128 + (n - 128)];
    g_w1[idx] = __float2half_rn(v);
}
__global__ void convert_w2(const float* __restrict__ Wl, const float* __restrict__ Wr) {
    int idx = blockIdx.x * blockDim.x + threadIdx.x;
    if (idx >= 64 * 128) return;
    int n = idx >> 7, k = idx & 127;
    float v = (n < 32) ? Wl[k * 32 + n] : Wr[k * 32 + (n - 32)];
    g_w2[idx] = __float2half_rn(v);
}

// ===== GEMM1: y1[M,256] = x[M,512] @ W1^T  (fp16, fused convert) ===========
// 256 threads, CTA tile 128(M) x 128(N), BK=32, 2 CTAs/SM target.
// stage: A 128*80 + B 128*80 = 20480 B; 2 stages = 40960 B dynamic smem.
#define G1_STAGE 20480
#define SM_G1 (2 * G1_STAGE)

__global__ __launch_bounds__(256, 2) void gemm1_mma(const float* __restrict__ x,
                                                    float* __restrict__ y1, int M) {
    extern __shared__ char smem[];
    const uint32_t sb = su32(smem);
    const int tid  = threadIdx.x;
    const int lane = tid & 31, wid = tid >> 5;
    const int wm = (wid & 3) * 32;
    const int wn = (wid >> 2) * 64;
    const int rowBase = blockIdx.y * 128;
    const int colBase = blockIdx.x * 128;

    float acc[2][8][4];
#pragma unroll
    for (int i = 0; i < 2; i++)
#pragma unroll
        for (int j = 0; j < 8; j++)
#pragma unroll
            for (int q = 0; q < 4; q++) acc[i][j][q] = 0.f;

    const int g4 = lane & 3, gID = lane >> 2;
    const int sel = lane >> 3;
    const uint32_t rowInSel = (uint32_t)((sel & 1) * 8 + (lane & 7));
    const uint32_t colSel = (uint32_t)((sel >> 1) * 16);
    const uint32_t aOff = (wm + rowInSel) * 80 + colSel;
    const uint32_t bOff = 10240 + (wn + rowInSel) * 80 + colSel;

    // A: 128 rows x 32 k fp32 -> 512 8-float chunks, 2/thread (rows r, r+64)
    const int arow0 = tid >> 2, aq = tid & 3;
    const int gra0 = rowBase + arow0, gra1 = gra0 + 64;
    const bool av0 = (gra0 < M), av1 = (gra1 < M);
    const size_t agi0 = (size_t)(av0 ? gra0 : 0) * 512 + aq * 8;
    const size_t agi1 = (size_t)(av1 ? gra1 : 0) * 512 + aq * 8;
    const uint32_t sAo0 = arow0 * 80 + aq * 16;
    const uint32_t sAo1 = (arow0 + 64) * 80 + aq * 16;
    // B: 128 rows x 32 halves -> 512 16B chunks, 2/thread
    const size_t bgi0 = (size_t)(colBase + arow0) * 512 + aq * 8;
    const size_t bgi1 = (size_t)(colBase + arow0 + 64) * 512 + aq * 8;
    const uint32_t sBo0 = 10240 + arow0 * 80 + aq * 16;
    const uint32_t sBo1 = 10240 + (arow0 + 64) * 80 + aq * 16;

    float4 ra00, ra01, ra10, ra11;
    uint4 rb0, rb1;
    const float4 zf4 = make_float4(0.f, 0.f, 0.f, 0.f);

    auto loadRegs = [&](int kt) {
        ra00 = av0 ? *(const float4*)(x + agi0 + kt)     : zf4;
        ra01 = av0 ? *(const float4*)(x + agi0 + kt + 4) : zf4;
        ra10 = av1 ? *(const float4*)(x + agi1 + kt)     : zf4;
        ra11 = av1 ? *(const float4*)(x + agi1 + kt + 4) : zf4;
        rb0 = *(const uint4*)(g_w1 + bgi0 + kt);
        rb1 = *(const uint4*)(g_w1 + bgi1 + kt);
    };
    auto storeStage = [&](int s) {
        char* st = smem + s * G1_STAGE;
        uint2 h0 = cvt4h(ra00), h1 = cvt4h(ra01);
        *(uint4*)(st + sAo0) = make_uint4(h0.x, h0.y, h1.x, h1.y);
        h0 = cvt4h(ra10); h1 = cvt4h(ra11);
        *(uint4*)(st + sAo1) = make_uint4(h0.x, h0.y, h1.x, h1.y);
        *(uint4*)(st + sBo0) = rb0;
        *(uint4*)(st + sBo1) = rb1;
    };

    loadRegs(0);
    storeStage(0);
    __syncthreads();

    for (int it = 0; it < 16; it++) {
        const int s = it & 1;
        if (it < 15) loadRegs((it + 1) * 32);

        const uint32_t Ab = sb + s * G1_STAGE;
#pragma unroll
        for (int kk2 = 0; kk2 < 2; kk2++) {
            uint32_t a[2][4];
            ldsm4(a[0], Ab + aOff + kk2 * 32);
            ldsm4(a[1], Ab + aOff + 1280 + kk2 * 32);
#pragma unroll
            for (int ntp = 0; ntp < 4; ntp++) {
                uint32_t b[4];
                ldsm4(b, Ab + bOff + ntp * 1280 + kk2 * 32);
                uint32_t b0[2] = {b[0], b[2]};
                uint32_t b1[2] = {b[1], b[3]};
                mma16816h(acc[0][2 * ntp],     a[0], b0);
                mma16816h(acc[1][2 * ntp],     a[1], b0);
                mma16816h(acc[0][2 * ntp + 1], a[0], b1);
                mma16816h(acc[1][2 * ntp + 1], a[1], b1);
            }
        }
        if (it < 15) storeStage(s ^ 1);
        __syncthreads();
    }

#pragma unroll
    for (int mt = 0; mt < 2; mt++) {
        int r0 = rowBase + wm + mt * 16 + gID;
#pragma unroll
        for (int nt = 0; nt < 8; nt++) {
            int cc = colBase + wn + nt * 8 + g4 * 2;
            if (r0 < M)
                *(float2*)(y1 + (size_t)r0 * 256 + cc) = make_float2(acc[mt][nt][0], acc[mt][nt][1]);
            if (r0 + 8 < M)
                *(float2*)(y1 + (size_t)(r0 + 8) * 256 + cc) = make_float2(acc[mt][nt][2], acc[mt][nt][3]);
        }
    }
}

// ===== GEMM2 (fused SAGE epilogue): h1 computed in A-load ===================
// h1[m][k] = relu(agg1[m][k]/max(cnt,1) + b1l[k] + y1[m][256*? right half]);
// y2[M,64] = h1 @ W2^T (single fp16).
__global__ __launch_bounds__(256) void gemm2_mma(const float* __restrict__ b1l,
                                                 float* __restrict__ y2, int M) {
    __shared__ __half sA[128][40], sB[64][40];

    const int tid  = threadIdx.x;
    const int lane = tid & 31, wid = tid >> 5;
    const int wm = (wid & 3) * 32;
    const int wn = (wid >> 2) * 32;
    const int rowBase = blockIdx.x * 128;

    float acc[2][4][4];
#pragma unroll
    for (int i = 0; i < 2; i++)
#pragma unroll
        for (int j = 0; j < 4; j++)
#pragma unroll
            for (int q = 0; q < 4; q++) acc[i][j][q] = 0.f;

    const int g4 = lane & 3, gID = lane >> 2;
    const int sel = lane >> 3;
    const uint32_t rowInSel = (uint32_t)((sel & 1) * 8 + (lane & 7));
    const uint32_t colSel = (uint32_t)((sel >> 1) * 16);

    const uint32_t aB = su32(sA), bB = su32(sB);
    const uint32_t aOff = (wm + rowInSel) * 80 + colSel;
    const uint32_t bOff = (wn + rowInSel) * 80 + colSel;

    // A rows handled by this thread: arow0, arow0+64 (fixed), chunk q = tid&3
    const int arow0 = tid >> 2, aq = tid & 3;
    const int gr0 = rowBase + arow0, gr1 = gr0 + 64;
    const bool av0 = (gr0 < M), av1 = (gr1 < M);
    const float inv0 = av0 ? 1.0f / fmaxf(g_cnt[gr0], 1.0f) : 0.f;
    const float inv1 = av1 ? 1.0f / fmaxf(g_cnt[gr1], 1.0f) : 0.f;

    for (int kt = 0; kt < 128; kt += 32) {
        const int kc = kt + aq * 8;
        float4 bb0 = *(const float4*)(b1l + kc);
        float4 bb1 = *(const float4*)(b1l + kc + 4);
#pragma unroll
        for (int p = 0; p < 2; p++) {
            const int gr = p ? gr1 : gr0;
            const bool av = p ? av1 : av0;
            const float inv = p ? inv1 : inv0;
            uint4 packed = make_uint4(0, 0, 0, 0);
            if (av) {
                float4 a0 = *(const float4*)(g_agg1 + (size_t)gr * 128 + kc);
                float4 a1 = *(const float4*)(g_agg1 + (size_t)gr * 128 + kc + 4);
                float4 r0 = *(const float4*)(g_y1 + (size_t)gr * 256 + 128 + kc);
                float4 r1 = *(const float4*)(g_y1 + (size_t)gr * 256 + 128 + kc + 4);
                float4 o0, o1;
                o0.x = fmaxf(a0.x * inv + bb0.x + r0.x, 0.f);
                o0.y = fmaxf(a0.y * inv + bb0.y + r0.y, 0.f);
                o0.z = fmaxf(a0.z * inv + bb0.z + r0.z, 0.f);
                o0.w = fmaxf(a0.w * inv + bb0.w + r0.w, 0.f);
                o1.x = fmaxf(a1.x * inv + bb1.x + r1.x, 0.f);
                o1.y = fmaxf(a1.y * inv + bb1.y + r1.y, 0.f);
                o1.z = fmaxf(a1.z * inv + bb1.z + r1.z, 0.f);
                o1.w = fmaxf(a1.w * inv + bb1.w + r1.w, 0.f);
                uint2 h0 = cvt4h(o0), h1 = cvt4h(o1);
                packed = make_uint4(h0.x, h0.y, h1.x, h1.y);
            }
            *(uint4*)&sA[arow0 + p * 64][aq * 8] = packed;
        }
        // B: 64 rows x 32 halves = 256 chunks -> 1/thread
        {
            int row = tid >> 2, q = tid & 3;
            if (row < 64)
                *(uint4*)&sB[row][q * 8] = *(const uint4*)(g_w2 + (size_t)row * 128 + kt + q * 8);
        }
        __syncthreads();

#pragma unroll
        for (int kk2 = 0; kk2 < 2; kk2++) {
            uint32_t a[2][4];
            ldsm4(a[0], aB + aOff + kk2 * 32);
            ldsm4(a[1], aB + aOff + 1280 + kk2 * 32);
#pragma unroll
            for (int ntp = 0; ntp < 2; ntp++) {
                uint32_t b[4];
                ldsm4(b, bB + bOff + ntp * 1280 + kk2 * 32);
                uint32_t b0[2] = {b[0], b[2]};
                uint32_t b1[2] = {b[1], b[3]};
                mma16816h(acc[0][2 * ntp],     a[0], b0);
                mma16816h(acc[1][2 * ntp],     a[1], b0);
                mma16816h(acc[0][2 * ntp + 1], a[0], b1);
                mma16816h(acc[1][2 * ntp + 1], a[1], b1);
            }
        }
        __syncthreads();
    }

#pragma unroll
    for (int mt = 0; mt < 2; mt++) {
        int r0 = rowBase + wm + mt * 16 + gID;
#pragma unroll
        for (int nt = 0; nt < 4; nt++) {
            int cc = wn + nt * 8 + g4 * 2;
            if (r0 < M)
                *(float2*)(y2 + (size_t)r0 * 64 + cc) = make_float2(acc[mt][nt][0], acc[mt][nt][1]);
            if (r0 + 8 < M)
                *(float2*)(y2 + (size_t)(r0 + 8) * 64 + cc) = make_float2(acc[mt][nt][2], acc[mt][nt][3]);
        }
    }
}

// ---------------- edge aggregation, layer 1 (128 feats, warp per edge) -----
__global__ void edge_agg1(const int* __restrict__ ei) {
    int gtid = blockIdx.x * blockDim.x + threadIdx.x;
    int e = gtid >> 5;
    int lane = gtid & 31;
    if (e >= N_EDGES) return;
    int src = ei[e];
    int dst = ei[N_EDGES + e];
    float4 v = *(const float4*)(g_y1 + (size_t)src * 256 + lane * 4);
    float* p = g_agg1 + (size_t)dst * 128 + lane * 4;
    asm volatile("red.global.add.v4.f32 [%0], {%1,%2,%3,%4};"
                 :: "l"(p), "f"(v.x), "f"(v.y), "f"(v.z), "f"(v.w) : "memory");
    if (lane == 0) atomicAdd(&g_cnt[dst], 1.0f);
}

// ---------------- edge aggregation, layer 2 (32 feats, 8 threads/edge) -----
__global__ void edge_agg2(const int* __restrict__ ei) {
    int gtid = blockIdx.x * blockDim.x + threadIdx.x;
    int e = gtid >> 3;
    int lane = gtid & 7;
    if (e >= N_EDGES) return;
    int src = ei[e];
    int dst = ei[N_EDGES + e];
    float4 v = *(const float4*)(g_y2 + (size_t)src * 64 + lane * 4);
    float* p = g_agg2 + (size_t)dst * 32 + lane * 4;
    asm volatile("red.global.add.v4.f32 [%0], {%1,%2,%3,%4};"
                 :: "l"(p), "f"(v.x), "f"(v.y), "f"(v.z), "f"(v.w) : "memory");
}

// ---------------- fused layer-2 epilogue + per-graph mean pool --------------
__global__ void pool_kernel(const int* __restrict__ batch, const float* __restrict__ b2l) {
    int f = threadIdx.x;           // 32
    int yid = threadIdx.y;         // 8
    int n0 = blockIdx.x * 512 + yid;
    float b = b2l[f];
    float acc = 0.f, cacc = 0.f;
    int cur = -1;
    for (int it = 0; it < 64; it++) {
        int n = n0 + it * 8;
        if (n < N_NODES) {
            int g = batch[n];
            if (g != cur) {
                if (cur >= 0) {
                    atomicAdd(&g_gsum[cur * 32 + f], acc);
                    if (f == 0) atomicAdd(&g_gcnt[cur], cacc);
                }
                cur = g; acc = 0.f; cacc = 0.f;
            }
            float inv = 1.0f / fmaxf(g_cnt[n], 1.0f);
            float v = g_agg2[(size_t)n * 32 + f] * inv + b + g_y2[(size_t)n * 64 + 32 + f];
            acc += fmaxf(v, 0.f);
            cacc += 1.f;
        }
    }
    if (cur >= 0) {
        atomicAdd(&g_gsum[cur * 32 + f], acc);
        if (f == 0) atomicAdd(&g_gcnt[cur], cacc);
    }
}

// ---------------- final tiny MLP (encoder head + decoder) ------------------
__global__ void mlp_kernel(const float* __restrict__ Wl1, const float* __restrict__ bl1,
                           const float* __restrict__ Wl2, const float* __restrict__ bl2,
                           const float* __restrict__ Wd1, const float* __restrict__ bd1,
                           const float* __restrict__ Wd2, const float* __restrict__ bd2,
                           const float* __restrict__ Wd3, const float* __restrict__ bd3,
                           float* __restrict__ out) {
    __shared__ float sWl1[1024], sWl2[512], sWd1[512], sWd2[1024], sWd3[1600];
    __shared__ float sbl1[32], sbl2[16], sbd1[32], sbd2[32], sbd3[50];
    int t = threadIdx.x;           // 64
    for (int i = t; i < 1024; i += 64) sWl1[i] = Wl1[i];
    for (int i = t; i < 512;  i += 64) sWl2[i] = Wl2[i];
    for (int i = t; i < 512;  i += 64) sWd1[i] = Wd1[i];
    for (int i = t; i < 1024; i += 64) sWd2[i] = Wd2[i];
    for (int i = t; i < 1600; i += 64) sWd3[i] = Wd3[i];
    if (t < 32) sbl1[t] = bl1[t];
    if (t < 16) sbl2[t] = bl2[t];
    if (t < 32) sbd1[t] = bd1[t];
    if (t < 32) sbd2[t] = bd2[t];
    for (int i = t; i < 50; i += 64) sbd3[i] = bd3[i];
    __syncthreads();
    if (t >= N_GRAPHS) return;

    float gv[32];
    float inv = 1.0f / fmaxf(g_gcnt[t], 1.0f);
#pragma unroll
    for (int i = 0; i < 32; i++) gv[i] = g_gsum[t * 32 + i] * inv;

    float a[32];
#pragma unroll
    for (int j = 0; j < 32; j++) {
        float s = sbl1[j];
#pragma unroll
        for (int i = 0; i < 32; i++) s = fmaf(gv[i], sWl1[i * 32 + j], s);
        a[j] = fmaxf(s, 0.f);
    }
    float enc[16];
#pragma unroll
    for (int j = 0; j < 16; j++) {
        float s = sbl2[j];
#pragma unroll
        for (int i = 0; i < 32; i++) s = fmaf(a[i], sWl2[i * 16 + j], s);
        enc[j] = s > 0.f ? s : 0.1f * s;
    }
#pragma unroll
    for (int j = 0; j < 16; j++) out[t * 16 + j] = enc[j];

    float z1[32];
#pragma unroll
    for (int j = 0; j < 32; j++) {
        float s = sbd1[j];
#pragma unroll
        for (int i = 0; i < 16; i++) s = fmaf(enc[i], sWd1[i * 32 + j], s);
        z1[j] = s > 0.f ? s : 0.1f * s;
    }
    float z2[32];
#pragma unroll
    for (int j = 0; j < 32; j++) {
        float s = sbd2[j];
#pragma unroll
        for (int i = 0; i < 32; i++) s = fmaf(z1[i], sWd2[i * 32 + j], s);
        z2[j] = s > 0.f ? s : 0.1f * s;
    }
#pragma unroll
    for (int j = 0; j < 50; j++) {
        float s = sbd3[j];
#pragma unroll
        for (int i = 0; i < 32; i++) s = fmaf(z2[i], sWd3[i * 50 + j], s);
        out[1024 + t * 50 + j] = s;
    }
}

// ---------------- launch ----------------------------------------------------
extern "C" void kernel_launch(void* const* d_in, const int* in_sizes, int n_in,
                              void* d_out, int out_size) {
    const float* x   = (const float*)d_in[0];
    const int*   ei  = (const int*)d_in[1];
    const int*   bat = (const int*)d_in[2];
    const float* W1l = (const float*)d_in[3];
    const float* b1l = (const float*)d_in[4];
    const float* W1r = (const float*)d_in[5];
    const float* W2l = (const float*)d_in[6];
    const float* b2l = (const float*)d_in[7];
    const float* W2r = (const float*)d_in[8];
    const float* Wl1 = (const float*)d_in[9];
    const float* bl1 = (const float*)d_in[10];
    const float* Wl2 = (const float*)d_in[11];
    const float* bl2 = (const float*)d_in[12];
    const float* Wd1 = (const float*)d_in[13];
    const float* bd1 = (const float*)d_in[14];
    const float* Wd2 = (const float*)d_in[15];
    const float* bd2 = (const float*)d_in[16];
    const float* Wd3 = (const float*)d_in[17];
    const float* bd3 = (const float*)d_in[18];
    float* out = (float*)d_out;

    float *p_y1, *p_y2;
    cudaGetSymbolAddress((void**)&p_y1, g_y1);
    cudaGetSymbolAddress((void**)&p_y2, g_y2);

    cudaFuncSetAttribute(gemm1_mma, cudaFuncAttributeMaxDynamicSharedMemorySize, SM_G1);

    zero_kernel<<<1184, 256>>>();
    convert_w<<<512, 256>>>(W1l, W1r);
    convert_w2<<<32, 256>>>(W2l, W2r);

    // GEMM1 (tensor pipe, fp16, fused convert; 2 CTAs/SM)
    {
        dim3 grid(2, (N_NODES + 127) / 128);
        gemm1_mma<<<grid, 256, SM_G1>>>(x, p_y1, N_NODES);
    }

    edge_agg1<<<50000, 256>>>(ei);

    // GEMM2 (tensor pipe, fused SAGE epilogue in A-load)
    gemm2_mma<<<(N_NODES + 127) / 128, 256>>>(b1l, p_y2, N_NODES);

    edge_agg2<<<12500, 256>>>(ei);

    {
        dim3 blk(32, 8);
        pool_kernel<<<(N_NODES + 511) / 512, blk>>>(bat, b2l);
    }

    mlp_kernel<<<1, 64>>>(Wl1, bl1, Wl2, bl2, Wd1, bd1, Wd2, bd2, Wd3, bd3, out);
}

// round 10
// speedup vs baseline: 1.1994x; 1.1994x over previous
#include <cuda_runtime.h>
#include <cuda_fp16.h>
#include <cstdint>

#define N_NODES  50000
#define N_EDGES  400000
#define N_GRAPHS 64

// ============================ device scratch ===============================
__device__ __half g_w1[256 * 512];         // [W1l|W1r]^T fp16  [256 n][512 k]
__device__ __half g_w2[64 * 128];          // [W2l|W2r]^T fp16  [64 n][128 k]
__device__ __half g_y1l[N_NODES * 128];    // x@W1l (fp16, for edge gather)
__device__ float  g_y1r[N_NODES * 128];    // x@W1r (fp32)
__device__ __half g_agg1[N_NODES * 128];   // fp16 edge-sum accumulator
__device__ float  g_cnt[N_NODES];
__device__ __half g_y2l[N_NODES * 32];     // h1@W2l (fp16)
__device__ float  g_y2r[N_NODES * 32];     // h1@W2r (fp32)
__device__ __half g_agg2[N_NODES * 32];    // fp16 edge-sum accumulator
__device__ float  g_gsum[N_GRAPHS * 32];
__device__ float  g_gcnt[N_GRAPHS];

// ============================ zero accumulators ============================
__global__ void zero_kernel() {
    size_t i = (size_t)blockIdx.x * blockDim.x + threadIdx.x;
    size_t stride = (size_t)gridDim.x * blockDim.x;
    for (size_t k = i; k < (size_t)N_NODES * 64; k += stride) ((uint32_t*)g_agg1)[k] = 0u;
    for (size_t k = i; k < (size_t)N_NODES * 16; k += stride) ((uint32_t*)g_agg2)[k] = 0u;
    for (size_t k = i; k < (size_t)N_NODES;      k += stride) g_cnt[k]  = 0.f;
    for (size_t k = i; k < (size_t)N_GRAPHS * 32; k += stride) g_gsum[k] = 0.f;
    for (size_t k = i; k < (size_t)N_GRAPHS;      k += stride) g_gcnt[k] = 0.f;
}

// ============================ helpers ======================================
__device__ __forceinline__ uint32_t su32(const void* p) {
    return (uint32_t)__cvta_generic_to_shared(p);
}
__device__ __forceinline__ uint32_t pack_h2(__half a, __half b) {
    __half2 t = __halves2half2(a, b);
    return *(uint32_t*)&t;
}
__device__ __forceinline__ uint2 cvt4h(float4 v) {
    return make_uint2(pack_h2(__float2half_rn(v.x), __float2half_rn(v.y)),
                      pack_h2(__float2half_rn(v.z), __float2half_rn(v.w)));
}
__device__ __forceinline__ void mma16816h(float* c, const uint32_t* a, const uint32_t* b) {
    asm volatile(
        "mma.sync.aligned.m16n8k16.row.col.f32.f16.f16.f32 "
        "{%0,%1,%2,%3}, {%4,%5,%6,%7}, {%8,%9}, {%0,%1,%2,%3};"
        : "+f"(c[0]), "+f"(c[1]), "+f"(c[2]), "+f"(c[3])
        : "r"(a[0]), "r"(a[1]), "r"(a[2]), "r"(a[3]), "r"(b[0]), "r"(b[1]));
}
__device__ __forceinline__ void ldsm4(uint32_t* r, uint32_t addr) {
    asm volatile("ldmatrix.sync.aligned.m8n8.x4.shared.b16 {%0,%1,%2,%3}, [%4];"
                 : "=r"(r[0]), "=r"(r[1]), "=r"(r[2]), "=r"(r[3]) : "r"(addr));
}
__device__ __forceinline__ void red_h8(__half* p, uint4 v) {
    asm volatile("red.global.add.noftz.v4.f16x2 [%0], {%1,%2,%3,%4};"
                 :: "l"(p), "r"(v.x), "r"(v.y), "r"(v.z), "r"(v.w) : "memory");
}

// ==================== weight conversions (fp16) =============================
__global__ void convert_w(const float* __restrict__ Wl, const float* __restrict__ Wr) {
    int idx = blockIdx.x * blockDim.x + threadIdx.x;
    if (idx >= 256 * 512) return;
    int n = idx >> 9, k = idx & 511;
    float v = (n < 128) ? Wl[k * 128 + n] : Wr[k * 128 + (n - 128)];
    g_w1[idx] = __float2half_rn(v);
}
__global__ void convert_w2(const float* __restrict__ Wl, const float* __restrict__ Wr) {
    int idx = blockIdx.x * blockDim.x + threadIdx.x;
    if (idx >= 64 * 128) return;
    int n = idx >> 7, k = idx & 127;
    float v = (n < 32) ? Wl[k * 32 + n] : Wr[k * 32 + (n - 32)];
    g_w2[idx] = __float2half_rn(v);
}

// ===== GEMM1: [y1l|y1r] = x[M,512] @ W1^T  (fp16, fused convert; R8 cfg) ===
// 512 threads, CTA tile 128(M) x 256(N), BK=32, 2-stage LDG->reg(cvt)->STS.
#define G1_STAGE 30720
#define SM_G1 (2 * G1_STAGE)

__global__ __launch_bounds__(512) void gemm1_mma(const float* __restrict__ x, int M) {
    extern __shared__ char smem[];
    const uint32_t sb = su32(smem);
    const int tid  = threadIdx.x;
    const int lane = tid & 31, wid = tid >> 5;
    const int wm = (wid & 3) * 32;
    const int wn = (wid >> 2) * 64;
    const int rowBase = blockIdx.x * 128;

    float acc[2][8][4];
#pragma unroll
    for (int i = 0; i < 2; i++)
#pragma unroll
        for (int j = 0; j < 8; j++)
#pragma unroll
            for (int q = 0; q < 4; q++) acc[i][j][q] = 0.f;

    const int g4 = lane & 3, gID = lane >> 2;
    const int sel = lane >> 3;
    const uint32_t rowInSel = (uint32_t)((sel & 1) * 8 + (lane & 7));
    const uint32_t colSel = (uint32_t)((sel >> 1) * 16);
    const uint32_t aOff = (wm + rowInSel) * 80 + colSel;
    const uint32_t bOff = 10240 + (wn + rowInSel) * 80 + colSel;

    const int arow = tid >> 2, aq = tid & 3;
    const int gra = rowBase + arow;
    const bool av = (gra < M);
    const size_t agi = (size_t)(av ? gra : 0) * 512 + aq * 8;
    const uint32_t sAo = arow * 80 + aq * 16;
    const size_t bgi0 = (size_t)(tid >> 2) * 512 + (tid & 3) * 8;
    const size_t bgi1 = (size_t)((tid >> 2) + 128) * 512 + (tid & 3) * 8;
    const uint32_t sBo0 = 10240 + (tid >> 2) * 80 + (tid & 3) * 16;
    const uint32_t sBo1 = 10240 + ((tid >> 2) + 128) * 80 + (tid & 3) * 16;

    float4 ra0, ra1;
    uint4 rb0, rb1;
    const float4 zf4 = make_float4(0.f, 0.f, 0.f, 0.f);

    auto loadRegs = [&](int kt) {
        ra0 = av ? *(const float4*)(x + agi + kt)     : zf4;
        ra1 = av ? *(const float4*)(x + agi + kt + 4) : zf4;
        rb0 = *(const uint4*)(g_w1 + bgi0 + kt);
        rb1 = *(const uint4*)(g_w1 + bgi1 + kt);
    };
    auto storeStage = [&](int s) {
        char* st = smem + s * G1_STAGE;
        uint2 h0 = cvt4h(ra0), h1 = cvt4h(ra1);
        *(uint4*)(st + sAo)  = make_uint4(h0.x, h0.y, h1.x, h1.y);
        *(uint4*)(st + sBo0) = rb0;
        *(uint4*)(st + sBo1) = rb1;
    };

    loadRegs(0);
    storeStage(0);
    __syncthreads();

    for (int it = 0; it < 16; it++) {
        const int s = it & 1;
        if (it < 15) loadRegs((it + 1) * 32);

        const uint32_t Ab = sb + s * G1_STAGE;
#pragma unroll
        for (int kk2 = 0; kk2 < 2; kk2++) {
            uint32_t a[2][4];
            ldsm4(a[0], Ab + aOff + kk2 * 32);
            ldsm4(a[1], Ab + aOff + 1280 + kk2 * 32);
#pragma unroll
            for (int ntp = 0; ntp < 4; ntp++) {
                uint32_t b[4];
                ldsm4(b, Ab + bOff + ntp * 1280 + kk2 * 32);
                uint32_t b0[2] = {b[0], b[2]};
                uint32_t b1[2] = {b[1], b[3]};
                mma16816h(acc[0][2 * ntp],     a[0], b0);
                mma16816h(acc[1][2 * ntp],     a[1], b0);
                mma16816h(acc[0][2 * ntp + 1], a[0], b1);
                mma16816h(acc[1][2 * ntp + 1], a[1], b1);
            }
        }
        if (it < 15) storeStage(s ^ 1);
        __syncthreads();
    }

    // epilogue: cols < 128 -> y1l fp16 ; cols >= 128 -> y1r fp32
#pragma unroll
    for (int mt = 0; mt < 2; mt++) {
        int r0 = rowBase + wm + mt * 16 + gID;
#pragma unroll
        for (int nt = 0; nt < 8; nt++) {
            int cc = wn + nt * 8 + g4 * 2;
            if (wn < 128) {
                uint32_t p0 = pack_h2(__float2half_rn(acc[mt][nt][0]),
                                      __float2half_rn(acc[mt][nt][1]));
                uint32_t p1 = pack_h2(__float2half_rn(acc[mt][nt][2]),
                                      __float2half_rn(acc[mt][nt][3]));
                if (r0 < M)     *(uint32_t*)(g_y1l + (size_t)r0 * 128 + cc) = p0;
                if (r0 + 8 < M) *(uint32_t*)(g_y1l + (size_t)(r0 + 8) * 128 + cc) = p1;
            } else {
                int cr = cc - 128;
                if (r0 < M)
                    *(float2*)(g_y1r + (size_t)r0 * 128 + cr) =
                        make_float2(acc[mt][nt][0], acc[mt][nt][1]);
                if (r0 + 8 < M)
                    *(float2*)(g_y1r + (size_t)(r0 + 8) * 128 + cr) =
                        make_float2(acc[mt][nt][2], acc[mt][nt][3]);
            }
        }
    }
}

// ===== GEMM2 (fused SAGE epilogue): h1 built in A-load ======================
__global__ __launch_bounds__(256) void gemm2_mma(const float* __restrict__ b1l, int M) {
    __shared__ __half sA[128][40], sB[64][40];

    const int tid  = threadIdx.x;
    const int lane = tid & 31, wid = tid >> 5;
    const int wm = (wid & 3) * 32;
    const int wn = (wid >> 2) * 32;
    const int rowBase = blockIdx.x * 128;

    float acc[2][4][4];
#pragma unroll
    for (int i = 0; i < 2; i++)
#pragma unroll
        for (int j = 0; j < 4; j++)
#pragma unroll
            for (int q = 0; q < 4; q++) acc[i][j][q] = 0.f;

    const int g4 = lane & 3, gID = lane >> 2;
    const int sel = lane >> 3;
    const uint32_t rowInSel = (uint32_t)((sel & 1) * 8 + (lane & 7));
    const uint32_t colSel = (uint32_t)((sel >> 1) * 16);

    const uint32_t aB = su32(sA), bB = su32(sB);
    const uint32_t aOff = (wm + rowInSel) * 80 + colSel;
    const uint32_t bOff = (wn + rowInSel) * 80 + colSel;

    const int arow0 = tid >> 2, aq = tid & 3;
    const int gr0 = rowBase + arow0, gr1 = gr0 + 64;
    const bool av0 = (gr0 < M), av1 = (gr1 < M);
    const float inv0 = av0 ? 1.0f / fmaxf(g_cnt[gr0], 1.0f) : 0.f;
    const float inv1 = av1 ? 1.0f / fmaxf(g_cnt[gr1], 1.0f) : 0.f;

    for (int kt = 0; kt < 128; kt += 32) {
        const int kc = kt + aq * 8;
        float4 bb0 = *(const float4*)(b1l + kc);
        float4 bb1 = *(const float4*)(b1l + kc + 4);
#pragma unroll
        for (int p = 0; p < 2; p++) {
            const int gr = p ? gr1 : gr0;
            const bool av = p ? av1 : av0;
            const float inv = p ? inv1 : inv0;
            uint4 packed = make_uint4(0, 0, 0, 0);
            if (av) {
                uint4 au = *(const uint4*)(g_agg1 + (size_t)gr * 128 + kc);
                const __half2* ah = (const __half2*)&au;
                float2 a0 = __half22float2(ah[0]), a1 = __half22float2(ah[1]);
                float2 a2 = __half22float2(ah[2]), a3 = __half22float2(ah[3]);
                float4 r0 = *(const float4*)(g_y1r + (size_t)gr * 128 + kc);
                float4 r1 = *(const float4*)(g_y1r + (size_t)gr * 128 + kc + 4);
                float4 o0, o1;
                o0.x = fmaxf(a0.x * inv + bb0.x + r0.x, 0.f);
                o0.y = fmaxf(a0.y * inv + bb0.y + r0.y, 0.f);
                o0.z = fmaxf(a1.x * inv + bb0.z + r0.z, 0.f);
                o0.w = fmaxf(a1.y * inv + bb0.w + r0.w, 0.f);
                o1.x = fmaxf(a2.x * inv + bb1.x + r1.x, 0.f);
                o1.y = fmaxf(a2.y * inv + bb1.y + r1.y, 0.f);
                o1.z = fmaxf(a3.x * inv + bb1.z + r1.z, 0.f);
                o1.w = fmaxf(a3.y * inv + bb1.w + r1.w, 0.f);
                uint2 h0 = cvt4h(o0), h1 = cvt4h(o1);
                packed = make_uint4(h0.x, h0.y, h1.x, h1.y);
            }
            *(uint4*)&sA[arow0 + p * 64][aq * 8] = packed;
        }
        {
            int row = tid >> 2, q = tid & 3;
            if (row < 64)
                *(uint4*)&sB[row][q * 8] = *(const uint4*)(g_w2 + (size_t)row * 128 + kt + q * 8);
        }
        __syncthreads();

#pragma unroll
        for (int kk2 = 0; kk2 < 2; kk2++) {
            uint32_t a[2][4];
            ldsm4(a[0], aB + aOff + kk2 * 32);
            ldsm4(a[1], aB + aOff + 1280 + kk2 * 32);
#pragma unroll
            for (int ntp = 0; ntp < 2; ntp++) {
                uint32_t b[4];
                ldsm4(b, bB + bOff + ntp * 1280 + kk2 * 32);
                uint32_t b0[2] = {b[0], b[2]};
                uint32_t b1[2] = {b[1], b[3]};
                mma16816h(acc[0][2 * ntp],     a[0], b0);
                mma16816h(acc[1][2 * ntp],     a[1], b0);
                mma16816h(acc[0][2 * ntp + 1], a[0], b1);
                mma16816h(acc[1][2 * ntp + 1], a[1], b1);
            }
        }
        __syncthreads();
    }

    // epilogue: cols < 32 -> y2l fp16 ; cols >= 32 -> y2r fp32
#pragma unroll
    for (int mt = 0; mt < 2; mt++) {
        int r0 = rowBase + wm + mt * 16 + gID;
#pragma unroll
        for (int nt = 0; nt < 4; nt++) {
            int cc = wn + nt * 8 + g4 * 2;
            if (cc < 32) {
                uint32_t p0 = pack_h2(__float2half_rn(acc[mt][nt][0]),
                                      __float2half_rn(acc[mt][nt][1]));
                uint32_t p1 = pack_h2(__float2half_rn(acc[mt][nt][2]),
                                      __float2half_rn(acc[mt][nt][3]));
                if (r0 < M)     *(uint32_t*)(g_y2l + (size_t)r0 * 32 + cc) = p0;
                if (r0 + 8 < M) *(uint32_t*)(g_y2l + (size_t)(r0 + 8) * 32 + cc) = p1;
            } else {
                int cr = cc - 32;
                if (r0 < M)
                    *(float2*)(g_y2r + (size_t)r0 * 32 + cr) =
                        make_float2(acc[mt][nt][0], acc[mt][nt][1]);
                if (r0 + 8 < M)
                    *(float2*)(g_y2r + (size_t)(r0 + 8) * 32 + cr) =
                        make_float2(acc[mt][nt][2], acc[mt][nt][3]);
            }
        }
    }
}

// -------- edge aggregation, layer 1 (128 fp16 feats, 16 threads/edge) ------
__global__ void edge_agg1(const int* __restrict__ ei) {
    int gtid = blockIdx.x * blockDim.x + threadIdx.x;
    int e = gtid >> 4;
    int lane = gtid & 15;
    if (e >= N_EDGES) return;
    int src = ei[e];
    int dst = ei[N_EDGES + e];
    uint4 v = *(const uint4*)(g_y1l + (size_t)src * 128 + lane * 8);
    red_h8(g_agg1 + (size_t)dst * 128 + lane * 8, v);
    if (lane == 0) atomicAdd(&g_cnt[dst], 1.0f);
}

// -------- edge aggregation, layer 2 (32 fp16 feats, 4 threads/edge) --------
__global__ void edge_agg2(const int* __restrict__ ei) {
    int gtid = blockIdx.x * blockDim.x + threadIdx.x;
    int e = gtid >> 2;
    int lane = gtid & 3;
    if (e >= N_EDGES) return;
    int src = ei[e];
    int dst = ei[N_EDGES + e];
    uint4 v = *(const uint4*)(g_y2l + (size_t)src * 32 + lane * 8);
    red_h8(g_agg2 + (size_t)dst * 32 + lane * 8, v);
}

// ---------------- fused layer-2 epilogue + per-graph mean pool --------------
__global__ void pool_kernel(const int* __restrict__ batch, const float* __restrict__ b2l) {
    int f = threadIdx.x;           // 32
    int yid = threadIdx.y;         // 8
    int n0 = blockIdx.x * 512 + yid;
    float b = b2l[f];
    float acc = 0.f, cacc = 0.f;
    int cur = -1;
    for (int it = 0; it < 64; it++) {
        int n = n0 + it * 8;
        if (n < N_NODES) {
            int g = batch[n];
            if (g != cur) {
                if (cur >= 0) {
                    atomicAdd(&g_gsum[cur * 32 + f], acc);
                    if (f == 0) atomicAdd(&g_gcnt[cur], cacc);
                }
                cur = g; acc = 0.f; cacc = 0.f;
            }
            float inv = 1.0f / fmaxf(g_cnt[n], 1.0f);
            float v = __half2float(g_agg2[(size_t)n * 32 + f]) * inv + b +
                      g_y2r[(size_t)n * 32 + f];
            acc += fmaxf(v, 0.f);
            cacc += 1.f;
        }
    }
    if (cur >= 0) {
        atomicAdd(&g_gsum[cur * 32 + f], acc);
        if (f == 0) atomicAdd(&g_gcnt[cur], cacc);
    }
}

// ---------------- final tiny MLP (encoder head + decoder) ------------------
__global__ void mlp_kernel(const float* __restrict__ Wl1, const float* __restrict__ bl1,
                           const float* __restrict__ Wl2, const float* __restrict__ bl2,
                           const float* __restrict__ Wd1, const float* __restrict__ bd1,
                           const float* __restrict__ Wd2, const float* __restrict__ bd2,
                           const float* __restrict__ Wd3, const float* __restrict__ bd3,
                           float* __restrict__ out) {
    __shared__ float sWl1[1024], sWl2[512], sWd1[512], sWd2[1024], sWd3[1600];
    __shared__ float sbl1[32], sbl2[16], sbd1[32], sbd2[32], sbd3[50];
    int t = threadIdx.x;           // 64
    for (int i = t; i < 1024; i += 64) sWl1[i] = Wl1[i];
    for (int i = t; i < 512;  i += 64) sWl2[i] = Wl2[i];
    for (int i = t; i < 512;  i += 64) sWd1[i] = Wd1[i];
    for (int i = t; i < 1024; i += 64) sWd2[i] = Wd2[i];
    for (int i = t; i < 1600; i += 64) sWd3[i] = Wd3[i];
    if (t < 32) sbl1[t] = bl1[t];
    if (t < 16) sbl2[t] = bl2[t];
    if (t < 32) sbd1[t] = bd1[t];
    if (t < 32) sbd2[t] = bd2[t];
    for (int i = t; i < 50; i += 64) sbd3[i] = bd3[i];
    __syncthreads();
    if (t >= N_GRAPHS) return;

    float gv[32];
    float inv = 1.0f / fmaxf(g_gcnt[t], 1.0f);
#pragma unroll
    for (int i = 0; i < 32; i++) gv[i] = g_gsum[t * 32 + i] * inv;

    float a[32];
#pragma unroll
    for (int j = 0; j < 32; j++) {
        float s = sbl1[j];
#pragma unroll
        for (int i = 0; i < 32; i++) s = fmaf(gv[i], sWl1[i * 32 + j], s);
        a[j] = fmaxf(s, 0.f);
    }
    float enc[16];
#pragma unroll
    for (int j = 0; j < 16; j++) {
        float s = sbl2[j];
#pragma unroll
        for (int i = 0; i < 32; i++) s = fmaf(a[i], sWl2[i * 16 + j], s);
        enc[j] = s > 0.f ? s : 0.1f * s;
    }
#pragma unroll
    for (int j = 0; j < 16; j++) out[t * 16 + j] = enc[j];

    float z1[32];
#pragma unroll
    for (int j = 0; j < 32; j++) {
        float s = sbd1[j];
#pragma unroll
        for (int i = 0; i < 16; i++) s = fmaf(enc[i], sWd1[i * 32 + j], s);
        z1[j] = s > 0.f ? s : 0.1f * s;
    }
    float z2[32];
#pragma unroll
    for (int j = 0; j < 32; j++) {
        float s = sbd2[j];
#pragma unroll
        for (int i = 0; i < 32; i++) s = fmaf(z1[i], sWd2[i * 32 + j], s);
        z2[j] = s > 0.f ? s : 0.1f * s;
    }
#pragma unroll
    for (int j = 0; j < 50; j++) {
        float s = sbd3[j];
#pragma unroll
        for (int i = 0; i < 32; i++) s = fmaf(z2[i], sWd3[i * 50 + j], s);
        out[1024 + t * 50 + j] = s;
    }
}

// ---------------- launch ----------------------------------------------------
extern "C" void kernel_launch(void* const* d_in, const int* in_sizes, int n_in,
                              void* d_out, int out_size) {
    const float* x   = (const float*)d_in[0];
    const int*   ei  = (const int*)d_in[1];
    const int*   bat = (const int*)d_in[2];
    const float* W1l = (const float*)d_in[3];
    const float* b1l = (const float*)d_in[4];
    const float* W1r = (const float*)d_in[5];
    const float* W2l = (const float*)d_in[6];
    const float* b2l = (const float*)d_in[7];
    const float* W2r = (const float*)d_in[8];
    const float* Wl1 = (const float*)d_in[9];
    const float* bl1 = (const float*)d_in[10];
    const float* Wl2 = (const float*)d_in[11];
    const float* bl2 = (const float*)d_in[12];
    const float* Wd1 = (const float*)d_in[13];
    const float* bd1 = (const float*)d_in[14];
    const float* Wd2 = (const float*)d_in[15];
    const float* bd2 = (const float*)d_in[16];
    const float* Wd3 = (const float*)d_in[17];
    const float* bd3 = (const float*)d_in[18];
    float* out = (float*)d_out;

    cudaFuncSetAttribute(gemm1_mma, cudaFuncAttributeMaxDynamicSharedMemorySize, SM_G1);

    zero_kernel<<<592, 256>>>();
    convert_w<<<512, 256>>>(W1l, W1r);
    convert_w2<<<32, 256>>>(W2l, W2r);

    // GEMM1 (tensor pipe, fp16, fused convert; writes y1l fp16 / y1r fp32)
    gemm1_mma<<<(N_NODES + 127) / 128, 512, SM_G1>>>(x, N_NODES);

    edge_agg1<<<25000, 256>>>(ei);   // fp16 v4 reductions, 16 thr/edge

    // GEMM2 (tensor pipe, fused SAGE epilogue; writes y2l fp16 / y2r fp32)
    gemm2_mma<<<(N_NODES + 127) / 128, 256>>>(b1l, N_NODES);

    edge_agg2<<<6250, 256>>>(ei);    // fp16 v4 reductions, 4 thr/edge

    {
        dim3 blk(32, 8);
        pool_kernel<<<(N_NODES + 511) / 512, blk>>>(bat, b2l);
    }

    mlp_kernel<<<1, 64>>>(Wl1, bl1, Wl2, bl2, Wd1, bd1, Wd2, bd2, Wd3, bd3, out);
}

// round 11
// speedup vs baseline: 1.2049x; 1.0046x over previous
#include <cuda_runtime.h>
#include <cuda_fp16.h>
#include <cstdint>

#define N_NODES  50000
#define N_EDGES  400000
#define N_GRAPHS 64

// ============================ device scratch ===============================
__device__ __half g_w1[256 * 512];         // [W1l|W1r]^T fp16  [256 n][512 k]
__device__ __half g_w2[64 * 128];          // [W2l|W2r]^T fp16  [64 n][128 k]
__device__ __half g_y1l[N_NODES * 128];    // x@W1l (fp16, for edge gather)
__device__ float  g_y1r[N_NODES * 128];    // x@W1r (fp32)
__device__ __half g_agg1[N_NODES * 128];   // fp16 edge-sum accumulator
__device__ float  g_cnt[N_NODES];
__device__ __half g_y2l[N_NODES * 32];     // h1@W2l (fp16)
__device__ float  g_y2r[N_NODES * 32];     // h1@W2r (fp32)
__device__ __half g_agg2[N_NODES * 32];    // fp16 edge-sum accumulator
__device__ float  g_gsum[N_GRAPHS * 32];
__device__ float  g_gcnt[N_GRAPHS];

// ============================ zero accumulators ============================
__global__ void zero_kernel() {
    size_t i = (size_t)blockIdx.x * blockDim.x + threadIdx.x;
    size_t stride = (size_t)gridDim.x * blockDim.x;
    for (size_t k = i; k < (size_t)N_NODES * 64; k += stride) ((uint32_t*)g_agg1)[k] = 0u;
    for (size_t k = i; k < (size_t)N_NODES * 16; k += stride) ((uint32_t*)g_agg2)[k] = 0u;
    for (size_t k = i; k < (size_t)N_NODES;      k += stride) g_cnt[k]  = 0.f;
    for (size_t k = i; k < (size_t)N_GRAPHS * 32; k += stride) g_gsum[k] = 0.f;
    for (size_t k = i; k < (size_t)N_GRAPHS;      k += stride) g_gcnt[k] = 0.f;
}

// ============================ helpers ======================================
__device__ __forceinline__ uint32_t su32(const void* p) {
    return (uint32_t)__cvta_generic_to_shared(p);
}
__device__ __forceinline__ uint32_t pack_h2(__half a, __half b) {
    __half2 t = __halves2half2(a, b);
    return *(uint32_t*)&t;
}
__device__ __forceinline__ uint2 cvt4h(float4 v) {
    return make_uint2(pack_h2(__float2half_rn(v.x), __float2half_rn(v.y)),
                      pack_h2(__float2half_rn(v.z), __float2half_rn(v.w)));
}
__device__ __forceinline__ void mma16816h(float* c, const uint32_t* a, const uint32_t* b) {
    asm volatile(
        "mma.sync.aligned.m16n8k16.row.col.f32.f16.f16.f32 "
        "{%0,%1,%2,%3}, {%4,%5,%6,%7}, {%8,%9}, {%0,%1,%2,%3};"
        : "+f"(c[0]), "+f"(c[1]), "+f"(c[2]), "+f"(c[3])
        : "r"(a[0]), "r"(a[1]), "r"(a[2]), "r"(a[3]), "r"(b[0]), "r"(b[1]));
}
__device__ __forceinline__ void ldsm4(uint32_t* r, uint32_t addr) {
    asm volatile("ldmatrix.sync.aligned.m8n8.x4.shared.b16 {%0,%1,%2,%3}, [%4];"
                 : "=r"(r[0]), "=r"(r[1]), "=r"(r[2]), "=r"(r[3]) : "r"(addr));
}
__device__ __forceinline__ void red_h8(__half* p, uint4 v) {
    asm volatile("red.global.add.noftz.v4.f16x2 [%0], {%1,%2,%3,%4};"
                 :: "l"(p), "r"(v.x), "r"(v.y), "r"(v.z), "r"(v.w) : "memory");
}

// ==================== weight conversions (fp16) =============================
__global__ void convert_w(const float* __restrict__ Wl, const float* __restrict__ Wr) {
    int idx = blockIdx.x * blockDim.x + threadIdx.x;
    if (idx >= 256 * 512) return;
    int n = idx >> 9, k = idx & 511;
    float v = (n < 128) ? Wl[k * 128 + n] : Wr[k * 128 + (n - 128)];
    g_w1[idx] = __float2half_rn(v);
}
__global__ void convert_w2(const float* __restrict__ Wl, const float* __restrict__ Wr) {
    int idx = blockIdx.x * blockDim.x + threadIdx.x;
    if (idx >= 64 * 128) return;
    int n = idx >> 7, k = idx & 127;
    float v = (n < 32) ? Wl[k * 32 + n] : Wr[k * 32 + (n - 32)];
    g_w2[idx] = __float2half_rn(v);
}

// ===== GEMM1: [y1l|y1r] = x[M,512] @ W1^T  (fp16, fused convert, BK=64) ====
// 512 threads, CTA tile 128(M) x 256(N), BK=64, 2-stage LDG->reg(cvt)->STS.
// stage: A 128*144 + B 256*144 = 55296 B; 2 stages = 110592 B dynamic smem.
#define G1_ROW 144
#define G1_STAGE 55296
#define SM_G1 (2 * G1_STAGE)

__global__ __launch_bounds__(512) void gemm1_mma(const float* __restrict__ x, int M) {
    extern __shared__ char smem[];
    const uint32_t sb = su32(smem);
    const int tid  = threadIdx.x;
    const int lane = tid & 31, wid = tid >> 5;
    const int wm = (wid & 3) * 32;
    const int wn = (wid >> 2) * 64;
    const int rowBase = blockIdx.x * 128;

    float acc[2][8][4];
#pragma unroll
    for (int i = 0; i < 2; i++)
#pragma unroll
        for (int j = 0; j < 8; j++)
#pragma unroll
            for (int q = 0; q < 4; q++) acc[i][j][q] = 0.f;

    const int g4 = lane & 3, gID = lane >> 2;
    const int sel = lane >> 3;
    const uint32_t rowInSel = (uint32_t)((sel & 1) * 8 + (lane & 7));
    const uint32_t colSel = (uint32_t)((sel >> 1) * 16);
    const uint32_t aOff = (wm + rowInSel) * G1_ROW + colSel;
    const uint32_t bOff = 18432 + (wn + rowInSel) * G1_ROW + colSel;

    // A: 128 rows x 64 fp32 -> thread t: row = t>>2, quad q = t&3 covers
    //    floats [q*16, q*16+16) = 4 float4 -> 2 uint4 halves.
    const int arow = tid >> 2, aq = tid & 3;
    const int gra = rowBase + arow;
    const bool av = (gra < M);
    const size_t agi = (size_t)(av ? gra : 0) * 512 + aq * 16;
    const uint32_t sAo = arow * G1_ROW + aq * 32;
    // B: 256 rows x 64 halves = 2048 16B-chunks -> 4/thread
    //    chunk c = tid + p*512: row = c>>3, q = c&7.
    const uint32_t bRow0 = tid >> 3, bQ = (uint32_t)(tid & 7);
    const size_t bgiBase = (size_t)bRow0 * 512 + bQ * 8;
    const uint32_t sBoBase = 18432 + bRow0 * G1_ROW + bQ * 16;

    float4 ra[4];
    uint4 rb[4];
    const float4 zf4 = make_float4(0.f, 0.f, 0.f, 0.f);

    auto loadRegs = [&](int kt) {
#pragma unroll
        for (int p = 0; p < 4; p++)
            ra[p] = av ? *(const float4*)(x + agi + kt + p * 4) : zf4;
#pragma unroll
        for (int p = 0; p < 4; p++)
            rb[p] = *(const uint4*)(g_w1 + bgiBase + (size_t)p * 64 * 512 + kt);
    };
    auto storeStage = [&](int s) {
        char* st = smem + s * G1_STAGE;
        uint2 h0 = cvt4h(ra[0]), h1 = cvt4h(ra[1]);
        *(uint4*)(st + sAo)      = make_uint4(h0.x, h0.y, h1.x, h1.y);
        h0 = cvt4h(ra[2]); h1 = cvt4h(ra[3]);
        *(uint4*)(st + sAo + 16) = make_uint4(h0.x, h0.y, h1.x, h1.y);
#pragma unroll
        for (int p = 0; p < 4; p++)
            *(uint4*)(st + sBoBase + p * (64 * G1_ROW)) = rb[p];
    };

    loadRegs(0);
    storeStage(0);
    __syncthreads();

    for (int it = 0; it < 8; it++) {
        const int s = it & 1;
        if (it < 7) loadRegs((it + 1) * 64);

        const uint32_t Ab = sb + s * G1_STAGE;
#pragma unroll
        for (int kk2 = 0; kk2 < 4; kk2++) {
            uint32_t a[2][4];
            ldsm4(a[0], Ab + aOff + kk2 * 32);
            ldsm4(a[1], Ab + aOff + 2304 + kk2 * 32);
#pragma unroll
            for (int ntp = 0; ntp < 4; ntp++) {
                uint32_t b[4];
                ldsm4(b, Ab + bOff + ntp * 2304 + kk2 * 32);
                uint32_t b0[2] = {b[0], b[2]};
                uint32_t b1[2] = {b[1], b[3]};
                mma16816h(acc[0][2 * ntp],     a[0], b0);
                mma16816h(acc[1][2 * ntp],     a[1], b0);
                mma16816h(acc[0][2 * ntp + 1], a[0], b1);
                mma16816h(acc[1][2 * ntp + 1], a[1], b1);
            }
        }
        if (it < 7) storeStage(s ^ 1);
        __syncthreads();
    }

    // epilogue: cols < 128 -> y1l fp16 ; cols >= 128 -> y1r fp32
#pragma unroll
    for (int mt = 0; mt < 2; mt++) {
        int r0 = rowBase + wm + mt * 16 + gID;
#pragma unroll
        for (int nt = 0; nt < 8; nt++) {
            int cc = wn + nt * 8 + g4 * 2;
            if (wn < 128) {
                uint32_t p0 = pack_h2(__float2half_rn(acc[mt][nt][0]),
                                      __float2half_rn(acc[mt][nt][1]));
                uint32_t p1 = pack_h2(__float2half_rn(acc[mt][nt][2]),
                                      __float2half_rn(acc[mt][nt][3]));
                if (r0 < M)     *(uint32_t*)(g_y1l + (size_t)r0 * 128 + cc) = p0;
                if (r0 + 8 < M) *(uint32_t*)(g_y1l + (size_t)(r0 + 8) * 128 + cc) = p1;
            } else {
                int cr = cc - 128;
                if (r0 < M)
                    *(float2*)(g_y1r + (size_t)r0 * 128 + cr) =
                        make_float2(acc[mt][nt][0], acc[mt][nt][1]);
                if (r0 + 8 < M)
                    *(float2*)(g_y1r + (size_t)(r0 + 8) * 128 + cr) =
                        make_float2(acc[mt][nt][2], acc[mt][nt][3]);
            }
        }
    }
}

// ===== GEMM2 (fused SAGE epilogue): h1 built in A-load ======================
__global__ __launch_bounds__(256) void gemm2_mma(const float* __restrict__ b1l, int M) {
    __shared__ __half sA[128][40], sB[64][40];

    const int tid  = threadIdx.x;
    const int lane = tid & 31, wid = tid >> 5;
    const int wm = (wid & 3) * 32;
    const int wn = (wid >> 2) * 32;
    const int rowBase = blockIdx.x * 128;

    float acc[2][4][4];
#pragma unroll
    for (int i = 0; i < 2; i++)
#pragma unroll
        for (int j = 0; j < 4; j++)
#pragma unroll
            for (int q = 0; q < 4; q++) acc[i][j][q] = 0.f;

    const int g4 = lane & 3, gID = lane >> 2;
    const int sel = lane >> 3;
    const uint32_t rowInSel = (uint32_t)((sel & 1) * 8 + (lane & 7));
    const uint32_t colSel = (uint32_t)((sel >> 1) * 16);

    const uint32_t aB = su32(sA), bB = su32(sB);
    const uint32_t aOff = (wm + rowInSel) * 80 + colSel;
    const uint32_t bOff = (wn + rowInSel) * 80 + colSel;

    const int arow0 = tid >> 2, aq = tid & 3;
    const int gr0 = rowBase + arow0, gr1 = gr0 + 64;
    const bool av0 = (gr0 < M), av1 = (gr1 < M);
    const float inv0 = av0 ? 1.0f / fmaxf(g_cnt[gr0], 1.0f) : 0.f;
    const float inv1 = av1 ? 1.0f / fmaxf(g_cnt[gr1], 1.0f) : 0.f;

    for (int kt = 0; kt < 128; kt += 32) {
        const int kc = kt + aq * 8;
        float4 bb0 = *(const float4*)(b1l + kc);
        float4 bb1 = *(const float4*)(b1l + kc + 4);
#pragma unroll
        for (int p = 0; p < 2; p++) {
            const int gr = p ? gr1 : gr0;
            const bool av = p ? av1 : av0;
            const float inv = p ? inv1 : inv0;
            uint4 packed = make_uint4(0, 0, 0, 0);
            if (av) {
                uint4 au = *(const uint4*)(g_agg1 + (size_t)gr * 128 + kc);
                const __half2* ah = (const __half2*)&au;
                float2 a0 = __half22float2(ah[0]), a1 = __half22float2(ah[1]);
                float2 a2 = __half22float2(ah[2]), a3 = __half22float2(ah[3]);
                float4 r0 = *(const float4*)(g_y1r + (size_t)gr * 128 + kc);
                float4 r1 = *(const float4*)(g_y1r + (size_t)gr * 128 + kc + 4);
                float4 o0, o1;
                o0.x = fmaxf(a0.x * inv + bb0.x + r0.x, 0.f);
                o0.y = fmaxf(a0.y * inv + bb0.y + r0.y, 0.f);
                o0.z = fmaxf(a1.x * inv + bb0.z + r0.z, 0.f);
                o0.w = fmaxf(a1.y * inv + bb0.w + r0.w, 0.f);
                o1.x = fmaxf(a2.x * inv + bb1.x + r1.x, 0.f);
                o1.y = fmaxf(a2.y * inv + bb1.y + r1.y, 0.f);
                o1.z = fmaxf(a3.x * inv + bb1.z + r1.z, 0.f);
                o1.w = fmaxf(a3.y * inv + bb1.w + r1.w, 0.f);
                uint2 h0 = cvt4h(o0), h1 = cvt4h(o1);
                packed = make_uint4(h0.x, h0.y, h1.x, h1.y);
            }
            *(uint4*)&sA[arow0 + p * 64][aq * 8] = packed;
        }
        {
            int row = tid >> 2, q = tid & 3;
            if (row < 64)
                *(uint4*)&sB[row][q * 8] = *(const uint4*)(g_w2 + (size_t)row * 128 + kt + q * 8);
        }
        __syncthreads();

#pragma unroll
        for (int kk2 = 0; kk2 < 2; kk2++) {
            uint32_t a[2][4];
            ldsm4(a[0], aB + aOff + kk2 * 32);
            ldsm4(a[1], aB + aOff + 1280 + kk2 * 32);
#pragma unroll
            for (int ntp = 0; ntp < 2; ntp++) {
                uint32_t b[4];
                ldsm4(b, bB + bOff + ntp * 1280 + kk2 * 32);
                uint32_t b0[2] = {b[0], b[2]};
                uint32_t b1[2] = {b[1], b[3]};
                mma16816h(acc[0][2 * ntp],     a[0], b0);
                mma16816h(acc[1][2 * ntp],     a[1], b0);
                mma16816h(acc[0][2 * ntp + 1], a[0], b1);
                mma16816h(acc[1][2 * ntp + 1], a[1], b1);
            }
        }
        __syncthreads();
    }

    // epilogue: cols < 32 -> y2l fp16 ; cols >= 32 -> y2r fp32
#pragma unroll
    for (int mt = 0; mt < 2; mt++) {
        int r0 = rowBase + wm + mt * 16 + gID;
#pragma unroll
        for (int nt = 0; nt < 4; nt++) {
            int cc = wn + nt * 8 + g4 * 2;
            if (cc < 32) {
                uint32_t p0 = pack_h2(__float2half_rn(acc[mt][nt][0]),
                                      __float2half_rn(acc[mt][nt][1]));
                uint32_t p1 = pack_h2(__float2half_rn(acc[mt][nt][2]),
                                      __float2half_rn(acc[mt][nt][3]));
                if (r0 < M)     *(uint32_t*)(g_y2l + (size_t)r0 * 32 + cc) = p0;
                if (r0 + 8 < M) *(uint32_t*)(g_y2l + (size_t)(r0 + 8) * 32 + cc) = p1;
            } else {
                int cr = cc - 32;
                if (r0 < M)
                    *(float2*)(g_y2r + (size_t)r0 * 32 + cr) =
                        make_float2(acc[mt][nt][0], acc[mt][nt][1]);
                if (r0 + 8 < M)
                    *(float2*)(g_y2r + (size_t)(r0 + 8) * 32 + cr) =
                        make_float2(acc[mt][nt][2], acc[mt][nt][3]);
            }
        }
    }
}

// -------- edge aggregation, layer 1 (128 fp16 feats, 16 threads/edge) ------
__global__ void edge_agg1(const int* __restrict__ ei) {
    int gtid = blockIdx.x * blockDim.x + threadIdx.x;
    int e = gtid >> 4;
    int lane = gtid & 15;
    if (e >= N_EDGES) return;
    int src = ei[e];
    int dst = ei[N_EDGES + e];
    uint4 v = *(const uint4*)(g_y1l + (size_t)src * 128 + lane * 8);
    red_h8(g_agg1 + (size_t)dst * 128 + lane * 8, v);
    if (lane == 0) atomicAdd(&g_cnt[dst], 1.0f);
}

// -------- edge aggregation, layer 2 (32 fp16 feats, 4 threads/edge) --------
__global__ void edge_agg2(const int* __restrict__ ei) {
    int gtid = blockIdx.x * blockDim.x + threadIdx.x;
    int e = gtid >> 2;
    int lane = gtid & 3;
    if (e >= N_EDGES) return;
    int src = ei[e];
    int dst = ei[N_EDGES + e];
    uint4 v = *(const uint4*)(g_y2l + (size_t)src * 32 + lane * 8);
    red_h8(g_agg2 + (size_t)dst * 32 + lane * 8, v);
}

// ---------------- fused layer-2 epilogue + per-graph mean pool --------------
__global__ void pool_kernel(const int* __restrict__ batch, const float* __restrict__ b2l) {
    int f = threadIdx.x;           // 32
    int yid = threadIdx.y;         // 8
    int n0 = blockIdx.x * 512 + yid;
    float b = b2l[f];
    float acc = 0.f, cacc = 0.f;
    int cur = -1;
    for (int it = 0; it < 64; it++) {
        int n = n0 + it * 8;
        if (n < N_NODES) {
            int g = batch[n];
            if (g != cur) {
                if (cur >= 0) {
                    atomicAdd(&g_gsum[cur * 32 + f], acc);
                    if (f == 0) atomicAdd(&g_gcnt[cur], cacc);
                }
                cur = g; acc = 0.f; cacc = 0.f;
            }
            float inv = 1.0f / fmaxf(g_cnt[n], 1.0f);
            float v = __half2float(g_agg2[(size_t)n * 32 + f]) * inv + b +
                      g_y2r[(size_t)n * 32 + f];
            acc += fmaxf(v, 0.f);
            cacc += 1.f;
        }
    }
    if (cur >= 0) {
        atomicAdd(&g_gsum[cur * 32 + f], acc);
        if (f == 0) atomicAdd(&g_gcnt[cur], cacc);
    }
}

// ---------------- final tiny MLP (encoder head + decoder) ------------------
__global__ void mlp_kernel(const float* __restrict__ Wl1, const float* __restrict__ bl1,
                           const float* __restrict__ Wl2, const float* __restrict__ bl2,
                           const float* __restrict__ Wd1, const float* __restrict__ bd1,
                           const float* __restrict__ Wd2, const float* __restrict__ bd2,
                           const float* __restrict__ Wd3, const float* __restrict__ bd3,
                           float* __restrict__ out) {
    __shared__ float sWl1[1024], sWl2[512], sWd1[512], sWd2[1024], sWd3[1600];
    __shared__ float sbl1[32], sbl2[16], sbd1[32], sbd2[32], sbd3[50];
    int t = threadIdx.x;           // 64
    for (int i = t; i < 1024; i += 64) sWl1[i] = Wl1[i];
    for (int i = t; i < 512;  i += 64) sWl2[i] = Wl2[i];
    for (int i = t; i < 512;  i += 64) sWd1[i] = Wd1[i];
    for (int i = t; i < 1024; i += 64) sWd2[i] = Wd2[i];
    for (int i = t; i < 1600; i += 64) sWd3[i] = Wd3[i];
    if (t < 32) sbl1[t] = bl1[t];
    if (t < 16) sbl2[t] = bl2[t];
    if (t < 32) sbd1[t] = bd1[t];
    if (t < 32) sbd2[t] = bd2[t];
    for (int i = t; i < 50; i += 64) sbd3[i] = bd3[i];
    __syncthreads();
    if (t >= N_GRAPHS) return;

    float gv[32];
    float inv = 1.0f / fmaxf(g_gcnt[t], 1.0f);
#pragma unroll
    for (int i = 0; i < 32; i++) gv[i] = g_gsum[t * 32 + i] * inv;

    float a[32];
#pragma unroll
    for (int j = 0; j < 32; j++) {
        float s = sbl1[j];
#pragma unroll
        for (int i = 0; i < 32; i++) s = fmaf(gv[i], sWl1[i * 32 + j], s);
        a[j] = fmaxf(s, 0.f);
    }
    float enc[16];
#pragma unroll
    for (int j = 0; j < 16; j++) {
        float s = sbl2[j];
#pragma unroll
        for (int i = 0; i < 32; i++) s = fmaf(a[i], sWl2[i * 16 + j], s);
        enc[j] = s > 0.f ? s : 0.1f * s;
    }
#pragma unroll
    for (int j = 0; j < 16; j++) out[t * 16 + j] = enc[j];

    float z1[32];
#pragma unroll
    for (int j = 0; j < 32; j++) {
        float s = sbd1[j];
#pragma unroll
        for (int i = 0; i < 16; i++) s = fmaf(enc[i], sWd1[i * 32 + j], s);
        z1[j] = s > 0.f ? s : 0.1f * s;
    }
    float z2[32];
#pragma unroll
    for (int j = 0; j < 32; j++) {
        float s = sbd2[j];
#pragma unroll
        for (int i = 0; i < 32; i++) s = fmaf(z1[i], sWd2[i * 32 + j], s);
        z2[j] = s > 0.f ? s : 0.1f * s;
    }
#pragma unroll
    for (int j = 0; j < 50; j++) {
        float s = sbd3[j];
#pragma unroll
        for (int i = 0; i < 32; i++) s = fmaf(z2[i], sWd3[i * 50 + j], s);
        out[1024 + t * 50 + j] = s;
    }
}

// ---------------- launch ----------------------------------------------------
extern "C" void kernel_launch(void* const* d_in, const int* in_sizes, int n_in,
                              void* d_out, int out_size) {
    const float* x   = (const float*)d_in[0];
    const int*   ei  = (const int*)d_in[1];
    const int*   bat = (const int*)d_in[2];
    const float* W1l = (const float*)d_in[3];
    const float* b1l = (const float*)d_in[4];
    const float* W1r = (const float*)d_in[5];
    const float* W2l = (const float*)d_in[6];
    const float* b2l = (const float*)d_in[7];
    const float* W2r = (const float*)d_in[8];
    const float* Wl1 = (const float*)d_in[9];
    const float* bl1 = (const float*)d_in[10];
    const float* Wl2 = (const float*)d_in[11];
    const float* bl2 = (const float*)d_in[12];
    const float* Wd1 = (const float*)d_in[13];
    const float* bd1 = (const float*)d_in[14];
    const float* Wd2 = (const float*)d_in[15];
    const float* bd2 = (const float*)d_in[16];
    const float* Wd3 = (const float*)d_in[17];
    const float* bd3 = (const float*)d_in[18];
    float* out = (float*)d_out;

    cudaFuncSetAttribute(gemm1_mma, cudaFuncAttributeMaxDynamicSharedMemorySize, SM_G1);

    zero_kernel<<<592, 256>>>();
    convert_w<<<512, 256>>>(W1l, W1r);
    convert_w2<<<32, 256>>>(W2l, W2r);

    // GEMM1 (tensor pipe, fp16, fused convert, BK=64)
    gemm1_mma<<<(N_NODES + 127) / 128, 512, SM_G1>>>(x, N_NODES);

    edge_agg1<<<25000, 256>>>(ei);   // fp16 v4 reductions, 16 thr/edge

    // GEMM2 (tensor pipe, fused SAGE epilogue)
    gemm2_mma<<<(N_NODES + 127) / 128, 256>>>(b1l, N_NODES);

    edge_agg2<<<6250, 256>>>(ei);    // fp16 v4 reductions, 4 thr/edge

    {
        dim3 blk(32, 8);
        pool_kernel<<<(N_NODES + 511) / 512, blk>>>(bat, b2l);
    }

    mlp_kernel<<<1, 64>>>(Wl1, bl1, Wl2, bl2, Wd1, bd1, Wd2, bd2, Wd3, bd3, out);
}